// round 1
// baseline (speedup 1.0000x reference)
#include <cuda_runtime.h>
#include <cstdint>

// Problem constants (fixed by setup_inputs)
#define BB 8
#define CC 256
#define HH 128
#define WW 128
#define HWSZ 16384          // H*W
#define KK 1280             // min(int(0.1*H*W), 1280)
#define PP 25               // 5x5 window
#define C4 64               // C/4 float4 per pixel row

// Output layout: concat(patches, topk_coords, offsets, calibrated_map) as f32
#define PATCH_OFF  ((size_t)0)
#define PATCH_CNT  ((size_t)BB * KK * PP * CC)               // 65,536,000
#define COORD_OFF  (PATCH_OFF + PATCH_CNT)                   // 65,536,000
#define COORD_CNT  ((size_t)BB * KK * 2)                     // 20,480
#define OFFS_OFF   (COORD_OFF + COORD_CNT)                   // 65,556,480
#define OFFS_CNT   ((size_t)PP * 2)                          // 50
#define CAL_OFF    (OFFS_OFF + OFFS_CNT)                     // 65,556,530

#define SORT_SMEM  (HWSZ * 8 + 1024 * 4)                     // keys + reduction

// Static device scratch (allocation-guard safe)
__device__ float g_nhwc[(size_t)BB * HWSZ * CC];             // 134 MB NHWC copy
__device__ int   g_centers[BB * KK];                         // packed (cy<<8)|cx

// ---------------------------------------------------------------------------
// Kernel 1: NCHW -> NHWC transpose, per batch treated as [C, HW] -> [HW, C]
// ---------------------------------------------------------------------------
__global__ void transpose_kernel(const float* __restrict__ in) {
    __shared__ float tile[32][33];
    int b  = blockIdx.z;
    int c0 = blockIdx.y * 32;
    int s0 = blockIdx.x * 32;
    int tx = threadIdx.x, ty = threadIdx.y;   // 32 x 8

    const float* src = in + (size_t)b * CC * HWSZ;
    #pragma unroll
    for (int i = 0; i < 32; i += 8)
        tile[ty + i][tx] = src[(size_t)(c0 + ty + i) * HWSZ + s0 + tx];
    __syncthreads();
    float* dst = g_nhwc + (size_t)b * HWSZ * CC;
    #pragma unroll
    for (int i = 0; i < 32; i += 8)
        dst[(size_t)(s0 + ty + i) * CC + c0 + tx] = tile[tx][ty + i];
}

// ---------------------------------------------------------------------------
// Kernel 2: per-batch softmax (temp 0.5) + full bitonic sort for exact top-K
// One block per batch, 1024 threads, keys in dynamic smem.
// Key = (~bits(soft) << 32) | idx  -> ascending sort gives descending soft,
// ties broken by ascending index (matches jax.lax.top_k stability).
// ---------------------------------------------------------------------------
__global__ void softmax_topk_kernel(const float* __restrict__ sal,
                                    const float* __restrict__ mlog,
                                    float* __restrict__ out) {
    extern __shared__ unsigned long long smem[];
    unsigned long long* keys = smem;                 // HWSZ entries
    float* red = (float*)(smem + HWSZ);              // 1024 floats

    int b   = blockIdx.x;
    int tid = threadIdx.x;
    const float* s = sal + (size_t)b * HWSZ;

    // pass 1: max of x = (sal + mask) / TEMP  (TEMP=0.5 -> *2, exact)
    float lmax = -3.402823466e38f;
    for (int i = tid; i < HWSZ; i += 1024) {
        float x = (s[i] + mlog[i]) * 2.0f;
        lmax = fmaxf(lmax, x);
    }
    red[tid] = lmax; __syncthreads();
    for (int o = 512; o; o >>= 1) {
        if (tid < o) red[tid] = fmaxf(red[tid], red[tid + o]);
        __syncthreads();
    }
    float mx = red[0]; __syncthreads();

    // pass 2: e = exp(x - max), sum; stash e bits in keys
    float lsum = 0.0f;
    for (int i = tid; i < HWSZ; i += 1024) {
        float x = (s[i] + mlog[i]) * 2.0f;
        float e = expf(x - mx);
        keys[i] = (unsigned long long)__float_as_uint(e);
        lsum += e;
    }
    red[tid] = lsum; __syncthreads();
    for (int o = 512; o; o >>= 1) {
        if (tid < o) red[tid] += red[tid + o];
        __syncthreads();
    }
    float sumv = red[0]; __syncthreads();

    // pass 3: soft = e / sum; write calibrated_map; build sort keys
    for (int i = tid; i < HWSZ; i += 1024) {
        float e = __uint_as_float((unsigned)keys[i]);
        float soft = e / sumv;
        out[CAL_OFF + (size_t)b * HWSZ + i] = soft;
        keys[i] = ((unsigned long long)(~__float_as_uint(soft)) << 32)
                  | (unsigned)i;
    }
    __syncthreads();

    // bitonic sort, ascending (keys are unique -> total order)
    for (unsigned kk = 2; kk <= HWSZ; kk <<= 1) {
        for (unsigned j = kk >> 1; j > 0; j >>= 1) {
            for (unsigned i = tid; i < HWSZ; i += 1024) {
                unsigned ixj = i ^ j;
                if (ixj > i) {
                    unsigned long long a = keys[i], c = keys[ixj];
                    bool up = ((i & kk) == 0);
                    if ((a > c) == up) { keys[i] = c; keys[ixj] = a; }
                }
            }
            __syncthreads();
        }
    }

    // top-K: coords out + packed centers for the gather kernel
    for (int m = tid; m < KK; m += 1024) {
        int idx = (int)(keys[m] & 0xFFFFFFFFull);
        int cy = min(max(idx >> 7, 2), HH - 1 - 2);
        int cx = min(max(idx & (WW - 1), 2), WW - 1 - 2);
        size_t o = COORD_OFF + ((size_t)b * KK + m) * 2;
        out[o + 0] = (float)cy;
        out[o + 1] = (float)cx;
        g_centers[b * KK + m] = (cy << 8) | cx;
    }
    if (b == 0 && tid < PP) {
        out[OFFS_OFF + tid * 2 + 0] = (float)(tid / 5 - 2);
        out[OFFS_OFF + tid * 2 + 1] = (float)(tid % 5 - 2);
    }
}

// ---------------------------------------------------------------------------
// Kernel 3: weighted patch gather. One block per (b,k); 256 threads.
// Warp 0 computes the 25 window weights; all threads stream 25 x 1KB rows
// (float4, fully coalesced read from NHWC and write to patches).
// ---------------------------------------------------------------------------
__global__ void gather_kernel(const float* __restrict__ cal,
                              const float* __restrict__ gamma,
                              float* __restrict__ patches) {
    int bk = blockIdx.x;
    int b  = bk / KK;
    int tid = threadIdx.x;

    __shared__ float w[PP];
    int packed = g_centers[bk];
    int cy = packed >> 8, cx = packed & 255;

    if (tid < 32) {
        int p = tid;
        int dy = 0, dx = 0;
        float sc = 0.0f;
        if (p < PP) {
            dy = p / 5 - 2; dx = p % 5 - 2;
            sc = cal[(size_t)b * HWSZ + (cy + dy) * WW + (cx + dx)];
        }
        float sum = sc;
        #pragma unroll
        for (int o = 16; o; o >>= 1) sum += __shfl_down_sync(0xffffffffu, sum, o);
        sum = __shfl_sync(0xffffffffu, sum, 0);
        if (p < PP) {
            float mean = sum / 25.0f;
            float g = gamma[0];
            float msk = 1.0f / (1.0f + expf(-g * (sc - mean)));
            float dist = sqrtf((float)(dy * dy + dx * dx));
            w[p] = msk * expf(-dist / 2.5f);   // LAMBDA*WIN = 2.5
        }
    }
    __syncthreads();

    int pr = tid >> 6;     // 0..3: row within group of 4
    int c4 = tid & 63;     // float4 index within the 256-channel row
    const float4* src_b = (const float4*)g_nhwc + (size_t)b * HWSZ * C4;
    float4* dst = (float4*)patches + (size_t)bk * PP * C4;

    #pragma unroll
    for (int pb = 0; pb < PP; pb += 4) {
        int p = pb + pr;
        if (p < PP) {
            int dy = p / 5 - 2, dx = p % 5 - 2;
            int lin = (cy + dy) * WW + (cx + dx);
            float4 v = src_b[(size_t)lin * C4 + c4];
            float wp = w[p];
            v.x *= wp; v.y *= wp; v.z *= wp; v.w *= wp;
            dst[(size_t)p * C4 + c4] = v;
        }
    }
}

// ---------------------------------------------------------------------------
extern "C" void kernel_launch(void* const* d_in, const int* in_sizes, int n_in,
                              void* d_out, int out_size) {
    const float* feat  = (const float*)d_in[0];
    const float* sal   = (const float*)d_in[1];
    const float* mlog  = (const float*)d_in[2];
    const float* gamma = (const float*)d_in[3];
    float* out = (float*)d_out;

    cudaFuncSetAttribute(softmax_topk_kernel,
                         cudaFuncAttributeMaxDynamicSharedMemorySize, SORT_SMEM);

    dim3 tb(32, 8);
    dim3 tg(HWSZ / 32, CC / 32, BB);
    transpose_kernel<<<tg, tb>>>(feat);

    softmax_topk_kernel<<<BB, 1024, SORT_SMEM>>>(sal, mlog, out);

    gather_kernel<<<BB * KK, 256>>>(out + CAL_OFF, gamma, out);
}

// round 2
// speedup vs baseline: 1.8190x; 1.8190x over previous
#include <cuda_runtime.h>
#include <cstdint>

// Problem constants (fixed by setup_inputs)
#define BB 8
#define CC 256
#define HH 128
#define WW 128
#define HWSZ 16384          // H*W
#define KK 1280             // min(int(0.1*H*W), 1280)
#define PP 25               // 5x5 window
#define C4 64               // C/4 float4 per pixel row
#define CAND 2048           // candidate buffer (power of 2 >= K + slack)

// Output layout: concat(patches, topk_coords, offsets, calibrated_map) as f32
#define PATCH_OFF  ((size_t)0)
#define PATCH_CNT  ((size_t)BB * KK * PP * CC)               // 65,536,000
#define COORD_OFF  (PATCH_OFF + PATCH_CNT)                   // 65,536,000
#define COORD_CNT  ((size_t)BB * KK * 2)                     // 20,480
#define OFFS_OFF   (COORD_OFF + COORD_CNT)                   // 65,556,480
#define OFFS_CNT   ((size_t)PP * 2)                          // 50
#define CAL_OFF    (OFFS_OFF + OFFS_CNT)                     // 65,556,530

// dynamic smem layout for sort kernel
#define SB_BYTES   (HWSZ * 4)            // sbits: 64KB
#define KY_BYTES   (CAND * 8)            // keys:  16KB
#define RD_BYTES   (1024 * 4)            // red:    4KB
#define HG_BYTES   (256 * 4)             // hist:   1KB
#define SORT_SMEM  (SB_BYTES + KY_BYTES + RD_BYTES + HG_BYTES + 64)

// Static device scratch (allocation-guard safe)
__device__ float g_nhwc[(size_t)BB * HWSZ * CC];             // 134 MB NHWC copy
__device__ int   g_centers[BB * KK];                         // packed (cy<<8)|cx

// ---------------------------------------------------------------------------
// Kernel 1: NCHW -> NHWC transpose, per batch treated as [C, HW] -> [HW, C]
// ---------------------------------------------------------------------------
__global__ void transpose_kernel(const float* __restrict__ in) {
    __shared__ float tile[32][33];
    int b  = blockIdx.z;
    int c0 = blockIdx.y * 32;
    int s0 = blockIdx.x * 32;
    int tx = threadIdx.x, ty = threadIdx.y;   // 32 x 8

    const float* src = in + (size_t)b * CC * HWSZ;
    #pragma unroll
    for (int i = 0; i < 32; i += 8)
        tile[ty + i][tx] = src[(size_t)(c0 + ty + i) * HWSZ + s0 + tx];
    __syncthreads();
    float* dst = g_nhwc + (size_t)b * HWSZ * CC;
    #pragma unroll
    for (int i = 0; i < 32; i += 8)
        dst[(size_t)(s0 + ty + i) * CC + c0 + tx] = tile[tx][ty + i];
}

// ---------------------------------------------------------------------------
// Kernel 2: per-batch softmax (temp 0.5) + radix-select top-K + small sort.
// One block per batch, 1024 threads.
//   1. softmax entirely in smem (values in sbits)
//   2. 4-round 8-bit radix select over positive-float bits -> exact Kth value T
//   3. collect items with bits >= T (count ~= K), pad to 2048
//   4. bitonic sort 2048 packed keys (~bits<<32 | idx) ascending
//      -> descending soft, ties ascending index (jax.lax.top_k semantics)
// ---------------------------------------------------------------------------
__global__ void softmax_topk_kernel(const float* __restrict__ sal,
                                    const float* __restrict__ mlog,
                                    float* __restrict__ out) {
    extern __shared__ char smem_raw[];
    unsigned*            sbits = (unsigned*)smem_raw;
    unsigned long long*  keys  = (unsigned long long*)(smem_raw + SB_BYTES);
    float*               red   = (float*)(smem_raw + SB_BYTES + KY_BYTES);
    int*                 hist  = (int*)(smem_raw + SB_BYTES + KY_BYTES + RD_BYTES);
    __shared__ int sh_prefix, sh_cnt;

    int b   = blockIdx.x;
    int tid = threadIdx.x;
    const float* s = sal + (size_t)b * HWSZ;

    // pass 1: x = (sal + mask) * 2 (TEMP=0.5); stash x; block max
    float lmax = -3.402823466e38f;
    for (int i = tid; i < HWSZ; i += 1024) {
        float x = (s[i] + mlog[i]) * 2.0f;
        ((float*)sbits)[i] = x;
        lmax = fmaxf(lmax, x);
    }
    red[tid] = lmax; __syncthreads();
    for (int o = 512; o; o >>= 1) {
        if (tid < o) red[tid] = fmaxf(red[tid], red[tid + o]);
        __syncthreads();
    }
    float mx = red[0]; __syncthreads();

    // pass 2: e = exp(x - max); overwrite; block sum
    float lsum = 0.0f;
    for (int i = tid; i < HWSZ; i += 1024) {
        float e = expf(((float*)sbits)[i] - mx);
        ((float*)sbits)[i] = e;
        lsum += e;
    }
    red[tid] = lsum; __syncthreads();
    for (int o = 512; o; o >>= 1) {
        if (tid < o) red[tid] += red[tid + o];
        __syncthreads();
    }
    float sumv = red[0]; __syncthreads();

    // pass 3: soft = e/sum -> calibrated map + float bits (positive: monotonic)
    for (int i = tid; i < HWSZ; i += 1024) {
        float soft = ((float*)sbits)[i] / sumv;
        out[CAL_OFF + (size_t)b * HWSZ + i] = soft;
        sbits[i] = __float_as_uint(soft);
    }
    __syncthreads();

    // radix select: find exact Kth-largest bit pattern T
    unsigned prefix = 0;
    int remaining = KK;
    #pragma unroll
    for (int round = 0; round < 4; round++) {
        int shift = 24 - 8 * round;
        for (int d = tid; d < 256; d += 1024) hist[d] = 0;
        __syncthreads();
        for (int i = tid; i < HWSZ; i += 1024) {
            unsigned v = sbits[i];
            bool match = (round == 0) ||
                         ((v >> (shift + 8)) == (prefix >> (shift + 8)));
            if (match) atomicAdd(&hist[(v >> shift) & 255], 1);
        }
        __syncthreads();
        if (tid == 0) {
            int cum = 0, bsel = 0;
            for (int d = 255; d >= 0; --d) {
                cum += hist[d];
                if (cum >= remaining) { bsel = d; cum -= hist[d]; break; }
            }
            sh_prefix = (int)(prefix | ((unsigned)bsel << shift));
            sh_cnt = remaining - cum;     // still needed within this bucket
        }
        __syncthreads();
        prefix = (unsigned)sh_prefix;
        remaining = sh_cnt;
        __syncthreads();
    }
    unsigned T = prefix;

    // collect all items with bits >= T (count == K for distinct values)
    if (tid == 0) sh_cnt = 0;
    __syncthreads();
    for (int i = tid; i < HWSZ; i += 1024) {
        unsigned v = sbits[i];
        if (v >= T) {
            int pos = atomicAdd(&sh_cnt, 1);
            if (pos < CAND)
                keys[pos] = ((unsigned long long)(~v) << 32) | (unsigned)i;
        }
    }
    __syncthreads();
    int cnt = min(sh_cnt, CAND);
    for (int i = cnt + tid; i < CAND; i += 1024)
        keys[i] = 0xFFFFFFFFFFFFFFFFull;
    __syncthreads();

    // bitonic sort of 2048 keys, ascending
    for (unsigned kk = 2; kk <= CAND; kk <<= 1) {
        for (unsigned j = kk >> 1; j > 0; j >>= 1) {
            for (unsigned i = tid; i < CAND; i += 1024) {
                unsigned ixj = i ^ j;
                if (ixj > i) {
                    unsigned long long a = keys[i], c = keys[ixj];
                    bool up = ((i & kk) == 0);
                    if ((a > c) == up) { keys[i] = c; keys[ixj] = a; }
                }
            }
            __syncthreads();
        }
    }

    // top-K: coords out + packed centers for the gather kernel
    for (int m = tid; m < KK; m += 1024) {
        int idx = (int)(keys[m] & 0xFFFFFFFFull);
        int cy = min(max(idx >> 7, 2), HH - 1 - 2);
        int cx = min(max(idx & (WW - 1), 2), WW - 1 - 2);
        size_t o = COORD_OFF + ((size_t)b * KK + m) * 2;
        out[o + 0] = (float)cy;
        out[o + 1] = (float)cx;
        g_centers[b * KK + m] = (cy << 8) | cx;
    }
    if (b == 0 && tid < PP) {
        out[OFFS_OFF + tid * 2 + 0] = (float)(tid / 5 - 2);
        out[OFFS_OFF + tid * 2 + 1] = (float)(tid % 5 - 2);
    }
}

// ---------------------------------------------------------------------------
// Kernel 3: weighted patch gather. One block per (b,k); 320 threads
// (5 p-groups x 64 float4 lanes -> 5 fully-active iterations over 25 rows).
// ---------------------------------------------------------------------------
__global__ void gather_kernel(const float* __restrict__ cal,
                              const float* __restrict__ gamma,
                              float* __restrict__ patches) {
    int bk = blockIdx.x;
    int b  = bk / KK;
    int tid = threadIdx.x;

    __shared__ float w[PP];
    int packed = g_centers[bk];
    int cy = packed >> 8, cx = packed & 255;

    if (tid < 32) {
        int p = tid;
        int dy = 0, dx = 0;
        float sc = 0.0f;
        if (p < PP) {
            dy = p / 5 - 2; dx = p % 5 - 2;
            sc = cal[(size_t)b * HWSZ + (cy + dy) * WW + (cx + dx)];
        }
        float sum = sc;
        #pragma unroll
        for (int o = 16; o; o >>= 1) sum += __shfl_down_sync(0xffffffffu, sum, o);
        sum = __shfl_sync(0xffffffffu, sum, 0);
        if (p < PP) {
            float mean = sum / 25.0f;
            float g = gamma[0];
            float msk = 1.0f / (1.0f + expf(-g * (sc - mean)));
            float dist = sqrtf((float)(dy * dy + dx * dx));
            w[p] = msk * expf(-dist / 2.5f);   // LAMBDA*WIN = 2.5
        }
    }
    __syncthreads();

    int pr = tid >> 6;     // 0..4: p-group
    int c4 = tid & 63;     // float4 index within the 256-channel row
    const float4* src_b = (const float4*)g_nhwc + (size_t)b * HWSZ * C4;
    float4* dst = (float4*)patches + (size_t)bk * PP * C4;

    #pragma unroll
    for (int pb = 0; pb < PP; pb += 5) {
        int p = pb + pr;
        int dy = p / 5 - 2, dx = p % 5 - 2;
        int lin = (cy + dy) * WW + (cx + dx);
        float4 v = src_b[(size_t)lin * C4 + c4];
        float wp = w[p];
        v.x *= wp; v.y *= wp; v.z *= wp; v.w *= wp;
        dst[(size_t)p * C4 + c4] = v;
    }
}

// ---------------------------------------------------------------------------
extern "C" void kernel_launch(void* const* d_in, const int* in_sizes, int n_in,
                              void* d_out, int out_size) {
    const float* feat  = (const float*)d_in[0];
    const float* sal   = (const float*)d_in[1];
    const float* mlog  = (const float*)d_in[2];
    const float* gamma = (const float*)d_in[3];
    float* out = (float*)d_out;

    cudaFuncSetAttribute(softmax_topk_kernel,
                         cudaFuncAttributeMaxDynamicSharedMemorySize, SORT_SMEM);

    dim3 tb(32, 8);
    dim3 tg(HWSZ / 32, CC / 32, BB);
    transpose_kernel<<<tg, tb>>>(feat);

    softmax_topk_kernel<<<BB, 1024, SORT_SMEM>>>(sal, mlog, out);

    gather_kernel<<<BB * KK, 320>>>(out + CAL_OFF, gamma, out);
}

// round 3
// speedup vs baseline: 1.8635x; 1.0245x over previous
#include <cuda_runtime.h>
#include <cstdint>

// Problem constants (fixed by setup_inputs)
#define BB 8
#define CC 256
#define HH 128
#define WW 128
#define HWSZ 16384          // H*W
#define KK 1280             // min(int(0.1*H*W), 1280)
#define PP 25               // 5x5 window
#define CAND 2048           // candidate buffer (power of 2 >= K + slack)
#define WSTRIDE 260         // smem row stride (floats): 65 words, float4-aligned

// Output layout: concat(patches, topk_coords, offsets, calibrated_map) as f32
#define PATCH_OFF  ((size_t)0)
#define PATCH_CNT  ((size_t)BB * KK * PP * CC)               // 65,536,000
#define COORD_OFF  (PATCH_OFF + PATCH_CNT)                   // 65,536,000
#define COORD_CNT  ((size_t)BB * KK * 2)                     // 20,480
#define OFFS_OFF   (COORD_OFF + COORD_CNT)                   // 65,556,480
#define OFFS_CNT   ((size_t)PP * 2)                          // 50
#define CAL_OFF    (OFFS_OFF + OFFS_CNT)                     // 65,556,530

// dynamic smem layout for topk kernel
#define SB_BYTES   (HWSZ * 4)            // sbits: 64KB
#define KY_BYTES   (CAND * 8)            // keys:  16KB
#define RD_BYTES   (1024 * 4)            // red:    4KB
#define HG_BYTES   (257 * 4 * 2)         // hist + suffix
#define SORT_SMEM  (SB_BYTES + KY_BYTES + RD_BYTES + HG_BYTES + 64)

// Static device scratch (allocation-guard safe)
__device__ int g_centers[BB * KK];       // packed (cy<<8)|cx

// ---------------------------------------------------------------------------
// Kernel 1: per-batch softmax (temp 0.5) + radix-select top-K + small sort.
// One block per batch, 1024 threads.
// ---------------------------------------------------------------------------
__global__ void softmax_topk_kernel(const float* __restrict__ sal,
                                    const float* __restrict__ mlog,
                                    float* __restrict__ out) {
    extern __shared__ char smem_raw[];
    unsigned*            sbits = (unsigned*)smem_raw;
    unsigned long long*  keys  = (unsigned long long*)(smem_raw + SB_BYTES);
    float*               red   = (float*)(smem_raw + SB_BYTES + KY_BYTES);
    int*                 hist  = (int*)(smem_raw + SB_BYTES + KY_BYTES + RD_BYTES);
    int*                 suf   = hist + 257;
    __shared__ int sh_prefix, sh_cnt;

    int b   = blockIdx.x;
    int tid = threadIdx.x;
    const float* s = sal + (size_t)b * HWSZ;

    // pass 1: x = (sal + mask) * 2 (TEMP=0.5); stash x; block max
    float lmax = -3.402823466e38f;
    for (int i = tid; i < HWSZ; i += 1024) {
        float x = (s[i] + mlog[i]) * 2.0f;
        ((float*)sbits)[i] = x;
        lmax = fmaxf(lmax, x);
    }
    red[tid] = lmax; __syncthreads();
    for (int o = 512; o; o >>= 1) {
        if (tid < o) red[tid] = fmaxf(red[tid], red[tid + o]);
        __syncthreads();
    }
    float mx = red[0]; __syncthreads();

    // pass 2: e = exp(x - max); overwrite; block sum
    float lsum = 0.0f;
    for (int i = tid; i < HWSZ; i += 1024) {
        float e = expf(((float*)sbits)[i] - mx);
        ((float*)sbits)[i] = e;
        lsum += e;
    }
    red[tid] = lsum; __syncthreads();
    for (int o = 512; o; o >>= 1) {
        if (tid < o) red[tid] += red[tid + o];
        __syncthreads();
    }
    float sumv = red[0]; __syncthreads();

    // pass 3: soft = e/sum -> calibrated map + float bits (positive: monotonic)
    for (int i = tid; i < HWSZ; i += 1024) {
        float soft = ((float*)sbits)[i] / sumv;
        out[CAL_OFF + (size_t)b * HWSZ + i] = soft;
        sbits[i] = __float_as_uint(soft);
    }
    __syncthreads();

    // radix select: exact Kth-largest bit pattern T
    unsigned prefix = 0;
    int remaining = KK;
    #pragma unroll
    for (int round = 0; round < 4; round++) {
        int shift = 24 - 8 * round;
        for (int d = tid; d < 256; d += 1024) hist[d] = 0;
        __syncthreads();
        for (int i = tid; i < HWSZ; i += 1024) {
            unsigned v = sbits[i];
            bool match = (round == 0) ||
                         ((v >> (shift + 8)) == (prefix >> (shift + 8)));
            if (match) atomicAdd(&hist[(v >> shift) & 255], 1);
        }
        __syncthreads();
        // suffix sum: suf[d] = sum_{e>=d} hist[e]  (Hillis-Steele on 256)
        if (tid < 256) suf[tid] = hist[tid];
        if (tid == 0) suf[256] = 0;
        __syncthreads();
        for (int st = 1; st < 256; st <<= 1) {
            int v = 0;
            if (tid < 256) v = suf[tid] + ((tid + st < 256) ? suf[tid + st] : 0);
            __syncthreads();
            if (tid < 256) suf[tid] = v;
            __syncthreads();
        }
        // select bucket: largest d with suf[d] >= remaining
        if (tid < 256) {
            bool sel = (suf[tid] >= remaining) &&
                       (tid == 255 || suf[tid + 1] < remaining);
            if (sel) {
                sh_prefix = (int)(prefix | ((unsigned)tid << shift));
                sh_cnt = remaining - suf[tid + 1];
            }
        }
        __syncthreads();
        prefix = (unsigned)sh_prefix;
        remaining = sh_cnt;
        __syncthreads();
    }
    unsigned T = prefix;

    // collect all items with bits >= T (count == K for distinct values)
    if (tid == 0) sh_cnt = 0;
    __syncthreads();
    for (int i = tid; i < HWSZ; i += 1024) {
        unsigned v = sbits[i];
        if (v >= T) {
            int pos = atomicAdd(&sh_cnt, 1);
            if (pos < CAND)
                keys[pos] = ((unsigned long long)(~v) << 32) | (unsigned)i;
        }
    }
    __syncthreads();
    int cnt = min(sh_cnt, CAND);
    for (int i = cnt + tid; i < CAND; i += 1024)
        keys[i] = 0xFFFFFFFFFFFFFFFFull;
    __syncthreads();

    // bitonic sort of 2048 keys ascending -> descending soft, ties asc index
    for (unsigned kk = 2; kk <= CAND; kk <<= 1) {
        for (unsigned j = kk >> 1; j > 0; j >>= 1) {
            for (unsigned i = tid; i < CAND; i += 1024) {
                unsigned ixj = i ^ j;
                if (ixj > i) {
                    unsigned long long a = keys[i], c = keys[ixj];
                    bool up = ((i & kk) == 0);
                    if ((a > c) == up) { keys[i] = c; keys[ixj] = a; }
                }
            }
            __syncthreads();
        }
    }

    // top-K: coords out + packed centers for the gather kernel
    for (int m = tid; m < KK; m += 1024) {
        int idx = (int)(keys[m] & 0xFFFFFFFFull);
        int cy = min(max(idx >> 7, 2), HH - 1 - 2);
        int cx = min(max(idx & (WW - 1), 2), WW - 1 - 2);
        size_t o = COORD_OFF + ((size_t)b * KK + m) * 2;
        out[o + 0] = (float)cy;
        out[o + 1] = (float)cx;
        g_centers[b * KK + m] = (cy << 8) | cx;
    }
    if (b == 0 && tid < PP) {
        out[OFFS_OFF + tid * 2 + 0] = (float)(tid / 5 - 2);
        out[OFFS_OFF + tid * 2 + 1] = (float)(tid % 5 - 2);
    }
}

// ---------------------------------------------------------------------------
// Kernel 2: fused transpose + weighted patch gather, reading NCHW directly.
// One block per (b,k); 320 threads (10 warps).
//   phase 1: stage window [25 p][256 c] into smem (row stride 260 floats),
//            reading feat[b][c][y][x] with p-fastest flattening so each warp
//            touches ~6 contiguous 5-float row segments.
//   phase 2: LDS.128 over consecutive words (conflict-free), apply weight,
//            coalesced STG.128 to patches[b][k][p][c].
// ---------------------------------------------------------------------------
__global__ void gather_kernel(const float* __restrict__ feat,
                              const float* __restrict__ cal,
                              const float* __restrict__ gamma,
                              float* __restrict__ patches) {
    __shared__ float win[PP * WSTRIDE];
    __shared__ float w[PP];

    int bk = blockIdx.x;
    int b  = bk / KK;
    int tid = threadIdx.x;

    int packed = g_centers[bk];
    int cy = packed >> 8, cx = packed & 255;
    // window origin in the image
    const float* src = feat + (size_t)b * CC * HWSZ + (cy - 2) * WW + (cx - 2);

    // weights (warp 0)
    if (tid < 32) {
        int p = tid;
        int dy = 0, dx = 0;
        float sc = 0.0f;
        if (p < PP) {
            dy = p / 5 - 2; dx = p % 5 - 2;
            sc = cal[(size_t)b * HWSZ + (cy + dy) * WW + (cx + dx)];
        }
        float sum = sc;
        #pragma unroll
        for (int o = 16; o; o >>= 1) sum += __shfl_down_sync(0xffffffffu, sum, o);
        sum = __shfl_sync(0xffffffffu, sum, 0);
        if (p < PP) {
            float mean = sum / 25.0f;
            float g = gamma[0];
            float msk = 1.0f / (1.0f + expf(-g * (sc - mean)));
            float dist = sqrtf((float)(dy * dy + dx * dx));
            w[p] = msk * expf(-dist / 2.5f);   // LAMBDA*WIN = 2.5
        }
    }

    // phase 1: stage window into smem. i = c*25 + p, 20 exact iterations.
    #pragma unroll 5
    for (int i = tid; i < CC * PP; i += 320) {
        int c = i / 25;
        int p = i - c * 25;
        int py = p / 5, px = p - py * 5;
        float v = src[(size_t)c * HWSZ + py * WW + px];
        win[p * WSTRIDE + c] = v;
    }
    __syncthreads();

    // phase 2: weighted, coalesced write. o = p*64 + c4, 5 exact iterations.
    float4* dst = (float4*)(patches + (size_t)bk * PP * CC);
    #pragma unroll
    for (int o = tid; o < PP * (CC / 4); o += 320) {
        int p  = o >> 6;
        int c4 = o & 63;
        float4 v = *(const float4*)&win[p * WSTRIDE + c4 * 4];
        float wp = w[p];
        v.x *= wp; v.y *= wp; v.z *= wp; v.w *= wp;
        dst[o] = v;
    }
}

// ---------------------------------------------------------------------------
extern "C" void kernel_launch(void* const* d_in, const int* in_sizes, int n_in,
                              void* d_out, int out_size) {
    const float* feat  = (const float*)d_in[0];
    const float* sal   = (const float*)d_in[1];
    const float* mlog  = (const float*)d_in[2];
    const float* gamma = (const float*)d_in[3];
    float* out = (float*)d_out;

    cudaFuncSetAttribute(softmax_topk_kernel,
                         cudaFuncAttributeMaxDynamicSharedMemorySize, SORT_SMEM);

    softmax_topk_kernel<<<BB, 1024, SORT_SMEM>>>(sal, mlog, out);

    gather_kernel<<<BB * KK, 320>>>(feat, out + CAL_OFF, gamma, out);
}